// round 6
// baseline (speedup 1.0000x reference)
#include <cuda_runtime.h>
#include <cstdint>

// ---------------- problem constants ----------------
#define BB   2
#define VV   4
#define FD   128
#define ED   128
#define NHN  7
#define NN6  196608
#define NN5  49152
#define NN4  12288
#define PFN  32768
#define PP5  8192
#define PP4  2048
#define OO5  4
#define OO4  16

#define THREADS 256
#define TILE_M  64

#define AP 132                       // sA / sI pitch (floats)
#define SA_FLOATS (TILE_M * AP)      // 8448 (33.8 KB)
#define SMEM_TOTAL (2 * SA_FLOATS * 4)   // 67584 B -> 3 CTAs/SM

typedef unsigned long long u64;

// scratch (device globals allowed)
__device__ float g_w5[BB * PP5 * OO5 * NHN];
__device__ float g_w4[BB * PP4 * OO4 * NHN];
__device__ float g_Wc[FD * ED];      // W with rna tf32 rounding

// ---------------- PTX helpers (baseline sm_80+ only) ----------------
__device__ __forceinline__ uint32_t f2tf32(float f) {
    uint32_t r; asm("cvt.rna.tf32.f32 %0, %1;" : "=r"(r) : "f"(f)); return r;
}
__device__ __forceinline__ u64 pack2(float s) {
    u64 r; unsigned ui = __float_as_uint(s);
    asm("mov.b64 %0, {%1, %1};" : "=l"(r) : "r"(ui));
    return r;
}
__device__ __forceinline__ u64 fma2(u64 a, u64 b, u64 c) {
    u64 d; asm("fma.rn.f32x2 %0, %1, %2, %3;" : "=l"(d) : "l"(a), "l"(b), "l"(c)); return d;
}
__device__ __forceinline__ void mma_tf32(float* c, const uint32_t* a,
                                         uint32_t b0, uint32_t b1) {
    asm volatile(
        "mma.sync.aligned.m16n8k8.row.col.f32.tf32.tf32.f32 "
        "{%0,%1,%2,%3}, {%4,%5,%6,%7}, {%8,%9}, {%0,%1,%2,%3};"
        : "+f"(c[0]), "+f"(c[1]), "+f"(c[2]), "+f"(c[3])
        : "r"(a[0]), "r"(a[1]), "r"(a[2]), "r"(a[3]), "r"(b0), "r"(b1));
}
__device__ __forceinline__ void cp16(uint32_t dst, const void* src) {
    asm volatile("cp.async.cg.shared.global [%0], [%1], 16;" :: "r"(dst), "l"(src) : "memory");
}
#define CP_COMMIT() asm volatile("cp.async.commit_group;" ::: "memory")
#define CP_WAIT0()  asm volatile("cp.async.wait_group 0;" ::: "memory")

// ---------------- pre-pass: interp weights + W tf32(rna) copy ----------------
__global__ void weights_kernel(const float* __restrict__ rd5, const float* __restrict__ m5,
                               const float* __restrict__ rd4, const float* __restrict__ m4,
                               const float* __restrict__ Wm)
{
    const int T5 = BB * PP5 * OO5;            // 65536
    const int T4 = BB * PP4 * OO4;            // 65536
    int t = blockIdx.x * blockDim.x + threadIdx.x;
    if (t < T5) {
        int pcb = t / OO5;
        const float* rd = rd5 + (size_t)t * NHN;
        const float* mm = m5 + (size_t)pcb * NHN;
        float w[NHN]; float s = 0.f;
#pragma unroll
        for (int n = 0; n < NHN; n++) { w[n] = 1.f / (1e-20f + rd[n] + mm[n] * 1e10f); s += w[n]; }
        float inv = 1.f / s;
#pragma unroll
        for (int n = 0; n < NHN; n++) g_w5[(size_t)t * NHN + n] = w[n] * inv;
    } else if (t < T5 + T4) {
        int tt = t - T5;
        int pcb = tt / OO4;
        const float* rd = rd4 + (size_t)tt * NHN;
        const float* mm = m4 + (size_t)pcb * NHN;
        float w[NHN]; float s = 0.f;
#pragma unroll
        for (int n = 0; n < NHN; n++) { w[n] = 1.f / (1e-20f + rd[n] + mm[n] * 1e10f); s += w[n]; }
        float inv = 1.f / s;
#pragma unroll
        for (int n = 0; n < NHN; n++) g_w4[(size_t)tt * NHN + n] = w[n] * inv;
    } else if (t < T5 + T4 + FD * ED) {
        int i = t - (T5 + T4);
        ((uint32_t*)g_Wc)[i] = f2tf32(Wm[i]);
    }
}

// ---------------- fused kernel ----------------
__global__ __launch_bounds__(THREADS, 3)
void embed_kernel(const float* __restrict__ table6, const float* __restrict__ table5,
                  const float* __restrict__ table4,
                  const float* __restrict__ bias,
                  const int* __restrict__ var_idx, const int* __restrict__ idx6,
                  const int* __restrict__ nh5, const int* __restrict__ nh4,
                  float* __restrict__ out)
{
    extern __shared__ float smem[];
    float* sA = smem;                    // [64][132]: gathered table6 rows (raw fp32)
    float* sI = sA + SA_FLOATS;          // [64][132]: interp staging

    const int tid  = threadIdx.x;
    const int lane = tid & 31;
    const int w    = tid >> 5;           // 0..7
    const int gid  = lane >> 2;
    const int tid4 = lane & 3;

    const int bv   = blockIdx.x >> 9;    // 512 tiles per (b,v)
    const int tile = blockIdx.x & 511;
    const int b = bv >> 2, v = bv & 3;
    const int vi = var_idx[b * VV + v];

    const float* tb6 = table6 + (size_t)vi * ((size_t)NN6 * FD);
    const float* tb5 = table5 + (size_t)vi * ((size_t)NN5 * FD);
    const float* tb4 = table4 + (size_t)vi * ((size_t)NN4 * FD);

    const uint32_t sA_u = (uint32_t)__cvta_generic_to_shared(sA);

    // ---- issue async staging of 64 gathered A rows ----
    {
        const int* i6 = idx6 + b * PFN + tile * TILE_M;
#pragma unroll
        for (int j = 0; j < 8; j++) {
            int rl = w * 8 + j;
            int row = i6[rl];
            cp16(sA_u + (uint32_t)(rl * AP * 4 + lane * 16),
                 tb6 + (size_t)row * FD + lane * 4);
        }
        CP_COMMIT();
    }

    // ---- interpolation (overlaps copies): 8 points per warp -> sI ----
    {
        const int pbase = tile * TILE_M + w * 8;      // multiple of 8
        const int pc5a = pbase >> 2;                  // two pc5 groups
        const int pc4  = pbase >> 4;
        const int o4   = pbase & 15;

        const int* np5 = nh5 + ((size_t)b * PP5 + pc5a) * NHN;
        const int* np4 = nh4 + ((size_t)b * PP4 + pc4) * NHN;
        const float* wp5 = g_w5 + ((size_t)(b * PP5 + pc5a)) * OO5 * NHN;
        const float* wp4 = g_w4 + (((size_t)(b * PP4 + pc4)) * OO4 + o4) * NHN;

        const ulonglong2 bias2 = ((const ulonglong2*)bias)[lane];
        u64 aL[8], aH[8];
#pragma unroll
        for (int pt = 0; pt < 8; pt++) { aL[pt] = bias2.x; aH[pt] = bias2.y; }

        // level-4: all 8 points share neighbor rows
        {
            ulonglong2 t4[NHN];
#pragma unroll
            for (int n = 0; n < NHN; n++)
                t4[n] = ((const ulonglong2*)(tb4 + (size_t)np4[n] * FD))[lane];
#pragma unroll
            for (int n = 0; n < NHN; n++) {
#pragma unroll
                for (int pt = 0; pt < 8; pt++) {
                    u64 wn = pack2(wp4[pt * NHN + n]);
                    aL[pt] = fma2(wn, t4[n].x, aL[pt]);
                    aH[pt] = fma2(wn, t4[n].y, aH[pt]);
                }
            }
        }
        // level-5 group A: points 0..3
        {
            ulonglong2 t5[NHN];
#pragma unroll
            for (int n = 0; n < NHN; n++)
                t5[n] = ((const ulonglong2*)(tb5 + (size_t)np5[n] * FD))[lane];
#pragma unroll
            for (int n = 0; n < NHN; n++) {
#pragma unroll
                for (int pt = 0; pt < 4; pt++) {
                    u64 wn = pack2(wp5[pt * NHN + n]);
                    aL[pt] = fma2(wn, t5[n].x, aL[pt]);
                    aH[pt] = fma2(wn, t5[n].y, aH[pt]);
                }
            }
        }
        // level-5 group B: points 4..7
        {
            ulonglong2 t5[NHN];
#pragma unroll
            for (int n = 0; n < NHN; n++)
                t5[n] = ((const ulonglong2*)(tb5 + (size_t)np5[NHN + n] * FD))[lane];
#pragma unroll
            for (int n = 0; n < NHN; n++) {
#pragma unroll
                for (int pt = 0; pt < 4; pt++) {
                    u64 wn = pack2(wp5[(OO5 + pt) * NHN + n]);
                    aL[4 + pt] = fma2(wn, t5[n].x, aL[4 + pt]);
                    aH[4 + pt] = fma2(wn, t5[n].y, aH[4 + pt]);
                }
            }
        }
#pragma unroll
        for (int pt = 0; pt < 8; pt++) {
            ulonglong2 o; o.x = aL[pt]; o.y = aH[pt];
            *(ulonglong2*)(sI + (size_t)(w * 8 + pt) * AP + lane * 4) = o;
        }
    }

    CP_WAIT0();
    __syncthreads();

    // ---- GEMM: warp (mw 0..1, nw 0..3) computes 32x32 of C = A @ W ----
    // A fragments from smem; B fragments straight from g_Wc via L1 (W is L1-hot).
    const int mw = w & 1, nw = w >> 1;
    const int MR = mw * 32, NC = nw * 32;
    float acc[2][4][4];
#pragma unroll
    for (int mi = 0; mi < 2; mi++)
#pragma unroll
        for (int ni = 0; ni < 4; ni++)
#pragma unroll
            for (int r = 0; r < 4; r++) acc[mi][ni][r] = 0.f;

    const uint32_t* Wg = (const uint32_t*)g_Wc;
#pragma unroll
    for (int k0 = 0; k0 < FD; k0 += 8) {
        uint32_t af[2][4];
#pragma unroll
        for (int mi = 0; mi < 2; mi++) {
            const uint32_t* ap = (const uint32_t*)sA + (MR + mi * 16 + gid) * AP + k0 + tid4;
            af[mi][0] = ap[0];
            af[mi][2] = ap[4];
            af[mi][1] = ap[8 * AP];
            af[mi][3] = ap[8 * AP + 4];
        }
        const uint32_t* bp0 = Wg + (size_t)(k0 + tid4) * ED + NC + gid;
#pragma unroll
        for (int ni = 0; ni < 4; ni++) {
            uint32_t b0 = __ldg(bp0 + ni * 8);
            uint32_t b1 = __ldg(bp0 + 4 * ED + ni * 8);
            mma_tf32(acc[0][ni], af[0], b0, b1);
            mma_tf32(acc[1][ni], af[1], b0, b1);
        }
    }
    __syncthreads();

    // ---- epilogue: C(regs) + interp(sI) -> gmem ----
    {
        float* ob = out + ((size_t)bv * PFN + (size_t)tile * TILE_M) * ED;
#pragma unroll
        for (int mi = 0; mi < 2; mi++) {
            const int row0 = MR + mi * 16 + gid;
            const int row1 = row0 + 8;
#pragma unroll
            for (int ni = 0; ni < 4; ni++) {
                const int col = NC + ni * 8 + 2 * tid4;
                float2 i0 = *(const float2*)(sI + (size_t)row0 * AP + col);
                float2 i1 = *(const float2*)(sI + (size_t)row1 * AP + col);
                float2 o0, o1;
                o0.x = acc[mi][ni][0] + i0.x;
                o0.y = acc[mi][ni][1] + i0.y;
                o1.x = acc[mi][ni][2] + i1.x;
                o1.y = acc[mi][ni][3] + i1.y;
                *(float2*)(ob + (size_t)row0 * ED + col) = o0;
                *(float2*)(ob + (size_t)row1 * ED + col) = o1;
            }
        }
    }
}

// ---------------- launch ----------------
extern "C" void kernel_launch(void* const* d_in, const int* in_sizes, int n_in,
                              void* d_out, int out_size)
{
    const float* table6 = (const float*)d_in[0];
    const float* table5 = (const float*)d_in[1];
    const float* table4 = (const float*)d_in[2];
    const float* Wm     = (const float*)d_in[3];
    const float* bias   = (const float*)d_in[4];
    const float* rd5    = (const float*)d_in[5];
    const float* rd4    = (const float*)d_in[6];
    const float* m5     = (const float*)d_in[7];
    const float* m4     = (const float*)d_in[8];
    const int*   vidx   = (const int*)d_in[9];
    const int*   idx6   = (const int*)d_in[10];
    const int*   nh5    = (const int*)d_in[11];
    const int*   nh4    = (const int*)d_in[12];
    float* out = (float*)d_out;

    {
        int total = BB * PP5 * OO5 + BB * PP4 * OO4 + FD * ED;
        weights_kernel<<<(total + 255) / 256, 256>>>(rd5, m5, rd4, m4, Wm);
    }
    {
        cudaFuncSetAttribute(embed_kernel,
                             cudaFuncAttributeMaxDynamicSharedMemorySize, SMEM_TOTAL);
        int grid = BB * VV * (PFN / TILE_M);   // 4096
        embed_kernel<<<grid, THREADS, SMEM_TOTAL>>>(table6, table5, table4, bias,
                                                    vidx, idx6, nh5, nh4, out);
    }
}

// round 7
// speedup vs baseline: 1.1254x; 1.1254x over previous
#include <cuda_runtime.h>
#include <cstdint>

// ---------------- problem constants ----------------
#define BB   2
#define VV   4
#define FD   128
#define ED   128
#define NHN  7
#define NN6  196608
#define NN5  49152
#define NN4  12288
#define PFN  32768
#define PP5  8192
#define PP4  2048
#define OO5  4
#define OO4  16

#define THREADS 256
#define TILE_M  64
#define NTILES  (BB * VV * (PFN / TILE_M))   // 4096
#define GRID    304                          // 152 SMs x 2 CTAs

#define AP 132                       // sA pitch (floats)
#define WP 132                       // sW pitch (floats)

#define SA_FLOATS (TILE_M * AP)      // 8448  (33.8 KB)
#define SW_FLOATS (ED * WP)          // 16896 (67.6 KB, n-major)
#define SMEM_TOTAL ((SA_FLOATS + SW_FLOATS) * 4)   // 101376 B -> 2 CTAs/SM

typedef unsigned long long u64;

// scratch (device globals allowed)
__device__ float g_w5[BB * PP5 * OO5 * NHN];
__device__ float g_w4[BB * PP4 * OO4 * NHN];
__device__ float g_Wt[ED * FD];      // W transposed (n-major), rna-tf32 rounded

// ---------------- PTX helpers (baseline sm_80+ only) ----------------
__device__ __forceinline__ uint32_t f2tf32(float f) {
    uint32_t r; asm("cvt.rna.tf32.f32 %0, %1;" : "=r"(r) : "f"(f)); return r;
}
__device__ __forceinline__ u64 pack2(float s) {
    u64 r; unsigned ui = __float_as_uint(s);
    asm("mov.b64 %0, {%1, %1};" : "=l"(r) : "r"(ui));
    return r;
}
__device__ __forceinline__ u64 fma2(u64 a, u64 b, u64 c) {
    u64 d; asm("fma.rn.f32x2 %0, %1, %2, %3;" : "=l"(d) : "l"(a), "l"(b), "l"(c)); return d;
}
__device__ __forceinline__ void mma_tf32(float* c, const uint32_t* a,
                                         uint32_t b0, uint32_t b1) {
    asm volatile(
        "mma.sync.aligned.m16n8k8.row.col.f32.tf32.tf32.f32 "
        "{%0,%1,%2,%3}, {%4,%5,%6,%7}, {%8,%9}, {%0,%1,%2,%3};"
        : "+f"(c[0]), "+f"(c[1]), "+f"(c[2]), "+f"(c[3])
        : "r"(a[0]), "r"(a[1]), "r"(a[2]), "r"(a[3]), "r"(b0), "r"(b1));
}
__device__ __forceinline__ void ldsm4(uint32_t* r, uint32_t addr) {
    asm volatile("ldmatrix.sync.aligned.m8n8.x4.shared.b16 {%0,%1,%2,%3}, [%4];"
                 : "=r"(r[0]), "=r"(r[1]), "=r"(r[2]), "=r"(r[3]) : "r"(addr));
}
__device__ __forceinline__ void cp16(uint32_t dst, const void* src) {
    asm volatile("cp.async.cg.shared.global [%0], [%1], 16;" :: "r"(dst), "l"(src) : "memory");
}
#define CP_COMMIT() asm volatile("cp.async.commit_group;" ::: "memory")
#define CP_WAIT0()  asm volatile("cp.async.wait_group 0;" ::: "memory")

// ---------------- pre-pass: interp weights + W transpose w/ rna tf32 ----------------
__global__ void weights_kernel(const float* __restrict__ rd5, const float* __restrict__ m5,
                               const float* __restrict__ rd4, const float* __restrict__ m4,
                               const float* __restrict__ Wm)
{
    const int T5 = BB * PP5 * OO5;            // 65536
    const int T4 = BB * PP4 * OO4;            // 65536
    int t = blockIdx.x * blockDim.x + threadIdx.x;
    if (t < T5) {
        int pcb = t / OO5;
        const float* rd = rd5 + (size_t)t * NHN;
        const float* mm = m5 + (size_t)pcb * NHN;
        float w[NHN]; float s = 0.f;
#pragma unroll
        for (int n = 0; n < NHN; n++) { w[n] = 1.f / (1e-20f + rd[n] + mm[n] * 1e10f); s += w[n]; }
        float inv = 1.f / s;
#pragma unroll
        for (int n = 0; n < NHN; n++) g_w5[(size_t)t * NHN + n] = w[n] * inv;
    } else if (t < T5 + T4) {
        int tt = t - T5;
        int pcb = tt / OO4;
        const float* rd = rd4 + (size_t)tt * NHN;
        const float* mm = m4 + (size_t)pcb * NHN;
        float w[NHN]; float s = 0.f;
#pragma unroll
        for (int n = 0; n < NHN; n++) { w[n] = 1.f / (1e-20f + rd[n] + mm[n] * 1e10f); s += w[n]; }
        float inv = 1.f / s;
#pragma unroll
        for (int n = 0; n < NHN; n++) g_w4[(size_t)tt * NHN + n] = w[n] * inv;
    } else if (t < T5 + T4 + FD * ED) {
        int i = t - (T5 + T4);
        int k = i >> 7, n = i & 127;
        ((uint32_t*)g_Wt)[n * FD + k] = f2tf32(Wm[i]);    // transpose to n-major
    }
}

// ---------------- persistent fused kernel ----------------
__global__ __launch_bounds__(THREADS, 2)
void embed_kernel(const float* __restrict__ table6, const float* __restrict__ table5,
                  const float* __restrict__ table4,
                  const float* __restrict__ bias,
                  const int* __restrict__ var_idx, const int* __restrict__ idx6,
                  const int* __restrict__ nh5, const int* __restrict__ nh4,
                  float* __restrict__ out)
{
    extern __shared__ float smem[];
    float* sA = smem;                    // [64][132]: gathered A rows; reused as interp staging
    float* sW = sA + SA_FLOATS;          // [128][132]: W^T n-major (tf32 bits)

    const int tid  = threadIdx.x;
    const int lane = tid & 31;
    const int w    = tid >> 5;           // 0..7
    const int gid  = lane >> 2;
    const int tid4 = lane & 3;

    const uint32_t sA_u = (uint32_t)__cvta_generic_to_shared(sA);
    const uint32_t sW_u = (uint32_t)__cvta_generic_to_shared(sW);

    // GEMM warp tiling: warp (mw 0..1, nw 0..3) -> 32x32 tile
    const int mw = w & 1, nw = w >> 1;
    const int MR = mw * 32, NC = nw * 32;

    // ldmatrix address bases (per-thread, fixed rows)
    const uint32_t aBase = sA_u + (uint32_t)(((MR + (lane & 15)) * AP + (lane >> 4) * 4) * 4);
    const uint32_t bBase = sW_u + (uint32_t)(((NC + lane) * WP) * 4);

    const ulonglong2 bias2 = ((const ulonglong2*)bias)[lane];

    // ---- prologue: stage W^T once + first tile's A rows ----
    int t = blockIdx.x;
    {
#pragma unroll
        for (int i = 0; i < 16; i++) {
            int c = tid + i * 256;                   // 4096 16B chunks
            int row = c >> 5, col = c & 31;
            cp16(sW_u + (uint32_t)(row * WP * 4 + col * 16),
                 g_Wt + (size_t)row * FD + col * 4);
        }
        if (t < NTILES) {
            const int bv = t >> 9, tl = t & 511;
            const int b = bv >> 2, v = bv & 3;
            const int vi = var_idx[b * VV + v];
            const float* tb6 = table6 + (size_t)vi * ((size_t)NN6 * FD);
            const int* i6 = idx6 + b * PFN + tl * TILE_M;
#pragma unroll
            for (int j = 0; j < 8; j++) {
                int rl = w * 8 + j;
                cp16(sA_u + (uint32_t)(rl * AP * 4 + lane * 16),
                     tb6 + (size_t)i6[rl] * FD + lane * 4);
            }
        }
        CP_COMMIT();
    }

    for (; t < NTILES; t += GRID) {
        const int bv = t >> 9, tl = t & 511;
        const int b = bv >> 2, v = bv & 3;
        const int vi = var_idx[b * VV + v];
        const float* tb5 = table5 + (size_t)vi * ((size_t)NN5 * FD);
        const float* tb4 = table4 + (size_t)vi * ((size_t)NN4 * FD);

        // ---- interpolation (overlaps A cp.async): 8 points per warp, in regs ----
        u64 aL[8], aH[8];
        {
            const int pbase = tl * TILE_M + w * 8;
            const int pc5a = pbase >> 2;
            const int pc4  = pbase >> 4;
            const int o4   = pbase & 15;

            const int* np5 = nh5 + ((size_t)b * PP5 + pc5a) * NHN;
            const int* np4 = nh4 + ((size_t)b * PP4 + pc4) * NHN;
            const float* wp5 = g_w5 + ((size_t)(b * PP5 + pc5a)) * OO5 * NHN;
            const float* wp4 = g_w4 + (((size_t)(b * PP4 + pc4)) * OO4 + o4) * NHN;

#pragma unroll
            for (int pt = 0; pt < 8; pt++) { aL[pt] = bias2.x; aH[pt] = bias2.y; }

            {   // level-4: all 8 points share neighbor rows
                ulonglong2 t4[NHN];
#pragma unroll
                for (int n = 0; n < NHN; n++)
                    t4[n] = ((const ulonglong2*)(tb4 + (size_t)np4[n] * FD))[lane];
#pragma unroll
                for (int n = 0; n < NHN; n++) {
#pragma unroll
                    for (int pt = 0; pt < 8; pt++) {
                        u64 wn = pack2(wp4[pt * NHN + n]);
                        aL[pt] = fma2(wn, t4[n].x, aL[pt]);
                        aH[pt] = fma2(wn, t4[n].y, aH[pt]);
                    }
                }
            }
            {   // level-5 group A: points 0..3
                ulonglong2 t5[NHN];
#pragma unroll
                for (int n = 0; n < NHN; n++)
                    t5[n] = ((const ulonglong2*)(tb5 + (size_t)np5[n] * FD))[lane];
#pragma unroll
                for (int n = 0; n < NHN; n++) {
#pragma unroll
                    for (int pt = 0; pt < 4; pt++) {
                        u64 wn = pack2(wp5[pt * NHN + n]);
                        aL[pt] = fma2(wn, t5[n].x, aL[pt]);
                        aH[pt] = fma2(wn, t5[n].y, aH[pt]);
                    }
                }
            }
            {   // level-5 group B: points 4..7
                ulonglong2 t5[NHN];
#pragma unroll
                for (int n = 0; n < NHN; n++)
                    t5[n] = ((const ulonglong2*)(tb5 + (size_t)np5[NHN + n] * FD))[lane];
#pragma unroll
                for (int n = 0; n < NHN; n++) {
#pragma unroll
                    for (int pt = 0; pt < 4; pt++) {
                        u64 wn = pack2(wp5[(OO5 + pt) * NHN + n]);
                        aL[4 + pt] = fma2(wn, t5[n].x, aL[4 + pt]);
                        aH[4 + pt] = fma2(wn, t5[n].y, aH[4 + pt]);
                    }
                }
            }
        }

        CP_WAIT0();
        __syncthreads();

        // ---- GEMM via ldmatrix + mma: 32x32 per warp ----
        float acc[2][4][4];
#pragma unroll
        for (int mi = 0; mi < 2; mi++)
#pragma unroll
            for (int ni = 0; ni < 4; ni++)
#pragma unroll
                for (int r = 0; r < 4; r++) acc[mi][ni][r] = 0.f;

#pragma unroll
        for (int k0 = 0; k0 < FD; k0 += 8) {
            uint32_t a0[4], a1[4], b0[4], b1[4];
            ldsm4(a0, aBase + k0 * 4);                     // mi=0 fragment
            ldsm4(a1, aBase + 16 * AP * 4 + k0 * 4);       // mi=1 fragment
            ldsm4(b0, bBase + k0 * 4);                     // b0 for ni=0..3
            ldsm4(b1, bBase + k0 * 4 + 16);                // b1 for ni=0..3
#pragma unroll
            for (int ni = 0; ni < 4; ni++) {
                mma_tf32(acc[0][ni], a0, b0[ni], b1[ni]);
                mma_tf32(acc[1][ni], a1, b0[ni], b1[ni]);
            }
        }
        __syncthreads();     // all sA reads done

        // ---- stage interp regs into sA (redistribution buffer) ----
#pragma unroll
        for (int pt = 0; pt < 8; pt++) {
            ulonglong2 o; o.x = aL[pt]; o.y = aH[pt];
            *(ulonglong2*)(sA + (size_t)(w * 8 + pt) * AP + lane * 4) = o;
        }
        __syncthreads();

        // ---- epilogue: C(regs) + interp(sA) -> gmem ----
        {
            float* ob = out + ((size_t)bv * PFN + (size_t)tl * TILE_M) * ED;
#pragma unroll
            for (int mi = 0; mi < 2; mi++) {
                const int row0 = MR + mi * 16 + gid;
                const int row1 = row0 + 8;
#pragma unroll
                for (int ni = 0; ni < 4; ni++) {
                    const int col = NC + ni * 8 + 2 * tid4;
                    float2 i0 = *(const float2*)(sA + (size_t)row0 * AP + col);
                    float2 i1 = *(const float2*)(sA + (size_t)row1 * AP + col);
                    float2 o0, o1;
                    o0.x = acc[mi][ni][0] + i0.x;
                    o0.y = acc[mi][ni][1] + i0.y;
                    o1.x = acc[mi][ni][2] + i1.x;
                    o1.y = acc[mi][ni][3] + i1.y;
                    *(float2*)(ob + (size_t)row0 * ED + col) = o0;
                    *(float2*)(ob + (size_t)row1 * ED + col) = o1;
                }
            }
        }
        __syncthreads();     // epilogue reads of sA done before next A staging

        // ---- prefetch next tile's A rows (overlaps next interp) ----
        int tn = t + GRID;
        if (tn < NTILES) {
            const int bvn = tn >> 9, tln = tn & 511;
            const int bn = bvn >> 2, vn = bvn & 3;
            const int vin = var_idx[bn * VV + vn];
            const float* tb6n = table6 + (size_t)vin * ((size_t)NN6 * FD);
            const int* i6n = idx6 + bn * PFN + tln * TILE_M;
#pragma unroll
            for (int j = 0; j < 8; j++) {
                int rl = w * 8 + j;
                cp16(sA_u + (uint32_t)(rl * AP * 4 + lane * 16),
                     tb6n + (size_t)i6n[rl] * FD + lane * 4);
            }
        }
        CP_COMMIT();
    }
}

// ---------------- launch ----------------
extern "C" void kernel_launch(void* const* d_in, const int* in_sizes, int n_in,
                              void* d_out, int out_size)
{
    const float* table6 = (const float*)d_in[0];
    const float* table5 = (const float*)d_in[1];
    const float* table4 = (const float*)d_in[2];
    const float* Wm     = (const float*)d_in[3];
    const float* bias   = (const float*)d_in[4];
    const float* rd5    = (const float*)d_in[5];
    const float* rd4    = (const float*)d_in[6];
    const float* m5     = (const float*)d_in[7];
    const float* m4     = (const float*)d_in[8];
    const int*   vidx   = (const int*)d_in[9];
    const int*   idx6   = (const int*)d_in[10];
    const int*   nh5    = (const int*)d_in[11];
    const int*   nh4    = (const int*)d_in[12];
    float* out = (float*)d_out;

    {
        int total = BB * PP5 * OO5 + BB * PP4 * OO4 + FD * ED;
        weights_kernel<<<(total + 255) / 256, 256>>>(rd5, m5, rd4, m4, Wm);
    }
    {
        cudaFuncSetAttribute(embed_kernel,
                             cudaFuncAttributeMaxDynamicSharedMemorySize, SMEM_TOTAL);
        embed_kernel<<<GRID, THREADS, SMEM_TOTAL>>>(table6, table5, table4, bias,
                                                    vidx, idx6, nh5, nh4, out);
    }
}